// round 15
// baseline (speedup 1.0000x reference)
#include <cuda_runtime.h>

#define NXg 512
#define NYg 512
#define NTg 300
#define NCELL (NXg * NYg)

#define TI 32                     // tile rows per block
#define TJ 32                     // tile cols per block
#define KSTEP 10
#define NPHASE (NTg / KSTEP)      // 30
#define RI (TI + 2 * KSTEP)       // 52 region rows
#define RJ (TJ + 2 * KSTEP)       // 52 region cols (13 float4 groups)
#define NACT 13                   // active column groups
#define NGX 16                    // blockDim.x (3 inert lanes for warp alignment)
#define NPAIR 26                  // row pairs (ty)
#define PITCH 56                  // floats per smem row (16B aligned)
#define SROWS (RI + 2)            // 54 rows incl guard top/bottom
#define SSZ (SROWS * PITCH)       // 3024 floats per level
#define COL0 4                    // smem float offset of region col 0
#define NTHR (NGX * NPAIR)        // 416 threads = 13 warps
#define NBX 16                    // blocks in j
#define NBY 16                    // blocks in i
#define NBLK (NBX * NBY)          // 256 blocks, 2 per SM co-resident

// Ping-pong pairs across phases + per-block phase flags (128B padded).
__device__ float g_u1a[NCELL];
__device__ float g_u2a[NCELL];
__device__ float g_u1b[NCELL];
__device__ float g_u2b[NCELL];
__device__ unsigned g_flags[NBLK * 32];

__global__ void wave_zero_kernel() {
    int idx = blockIdx.x * blockDim.x + threadIdx.x;
    if (idx < NBLK * 32) g_flags[idx] = 0u;
    if (idx < NCELL) {
        g_u1a[idx] = 0.0f;
        g_u2a[idx] = 0.0f;
    }
}

__device__ __forceinline__ void st_release_gpu(unsigned* p, unsigned v) {
    asm volatile("st.release.gpu.global.u32 [%0], %1;" :: "l"(p), "r"(v) : "memory");
}
__device__ __forceinline__ unsigned ld_acquire_gpu(const unsigned* p) {
    unsigned v;
    asm volatile("ld.acquire.gpu.global.u32 %0, [%1];" : "=r"(v) : "l"(p) : "memory");
    return v;
}
__device__ __forceinline__ void named_bar_sync(int id, int cnt) {
    asm volatile("bar.sync %0, %1;" :: "r"(id), "r"(cnt) : "memory");
}
__device__ __forceinline__ void named_bar_arrive(int id, int cnt) {
    asm volatile("bar.arrive %0, %1;" :: "r"(id), "r"(cnt) : "memory");
}

// PML ramp: b_vals[k] = 0.5 * (k/20)^3, k in [0,20]
__device__ __forceinline__ float pml_ramp(int k) {
    float t = (float)k * (1.0f / 20.0f);
    return 0.5f * t * t * t;
}

__device__ __forceinline__ float pml_b(int gi, int gj) {
    float bx = 0.0f, by = 0.0f;
    if (gi <= 20) bx = pml_ramp(20 - gi);
    else if (gi >= NXg - 22 && gi <= NXg - 2) bx = pml_ramp(gi - (NXg - 22));
    if (gj <= 20) by = pml_ramp(20 - gj);
    else if (gj >= NYg - 22 && gj <= NYg - 2) by = pml_ramp(gj - (NYg - 22));
    return sqrtf(bx * bx + by * by);
}

__global__ void __launch_bounds__(NTHR, 2)
wave_persist_kernel(const float* __restrict__ c2,
                    const float* __restrict__ msrc,
                    const float* __restrict__ xsrc,
                    float* __restrict__ d_final) {
    __shared__ __align__(16) float s0[SSZ];
    __shared__ __align__(16) float s1[SSZ];
    __shared__ float sX[NTg];
    __shared__ int sNbr[8];
    __shared__ int sNnbr;

    const int tx = threadIdx.x;            // 0..15 (13 active column groups)
    const int ty = threadIdx.y;            // 0..25 row pair
    const int tid = ty * NGX + tx;
    const bool act = (tx < NACT);

    const int bj = blockIdx.x, bi = blockIdx.y;
    const int gi0 = bi * TI;
    const int gj0 = bj * TJ;
    const int ri0 = gi0 - KSTEP;
    const int rj0 = gj0 - KSTEP;
    const int r0 = 2 * ty;                              // first owned region row
    const int base0 = (r0 + 1) * PITCH + COL0 + 4 * tx;
    const int base1 = base0 + PITCH;

    // ---- Band decomposition: 13 warps -> bands of {3,3,3,4} warps ----
    // warp = 2 consecutive row pairs (NGX=16 -> warp-aligned).
    // Band b uses barrier ids {1+2b, 2+2b}, alternating on step parity.
    const int warp = ty >> 1;              // 0..12
    const int band = (warp < 3) ? 0 : (warp < 6) ? 1 : (warp < 9) ? 2 : 3;
    const int bStart = band * 3;           // first warp of band (band3 starts at 9)
    const int bNw = (band == 3) ? 4 : 3;
    const int myId0 = 1 + 2 * band;
    // arrivals INTO band b: last warp of b-1 and first warp of b+1
    const int myCnt = 32 * bNw + (band > 0 ? 32 : 0) + (band < 3 ? 32 : 0);
    const bool arrUp = (warp == bStart && band > 0);
    const bool arrDn = (warp == bStart + bNw - 1 && band < 3);
    const int arrBand = arrUp ? band - 1 : band + 1;
    const int arrNw = (arrBand == 3) ? 4 : 3;
    const int arrCnt = 32 * arrNw + (arrBand > 0 ? 32 : 0) + (arrBand < 3 ? 32 : 0);
    const int arrId0 = 1 + 2 * arrBand;
    const bool doArr = arrUp || arrDn;

    // Neighbor list (<=8) for the inter-block flag handshake.
    if (tid == 0) {
        int n = 0;
        for (int di = -1; di <= 1; ++di)
            for (int dj = -1; dj <= 1; ++dj) {
                if (di == 0 && dj == 0) continue;
                int ni = bi + di, nj = bj + dj;
                if (ni >= 0 && ni < NBY && nj >= 0 && nj < NBX)
                    sNbr[n++] = (ni * NBX + nj) * 32;
            }
        sNnbr = n;
    }

    // Preload the full source series once.
    for (int k = tid; k < NTg; k += NTHR) sX[k] = xsrc[k];

    // Zero both smem levels incl. guards (guards stay 0 forever).
    for (int k = tid; k < SSZ; k += NTHR) { s0[k] = 0.0f; s1[k] = 0.0f; }

    // ---- One-time: coefficients + cell metadata into registers ----
    float cur[2][4], old[2][4];
    float cP4[2][4], cQ[2][4], cRc[2][4], cSb[2][4];
    int gidx[2][4];
    bool inDom[2][4], inTile[2][4];
    #pragma unroll
    for (int r = 0; r < 2; ++r) {
        int rr = r0 + r;
        int gi = ri0 + rr;
        #pragma unroll
        for (int i = 0; i < 4; ++i) {
            int cc = 4 * tx + i;
            int gj = rj0 + cc;
            bool in = act && (cc < RJ) &&
                      ((unsigned)gi < NXg) && ((unsigned)gj < NYg);
            inDom[r][i] = in;
            inTile[r][i] = in && (rr >= KSTEP) && (rr < KSTEP + TI) &&
                           (cc >= KSTEP) && (cc < KSTEP + TJ);
            int g = in ? (gi * NYg + gj) : 0;
            gidx[r][i] = g;
            float P4 = 0.0f, Qv = 0.0f, Rcv = 0.0f, Sbv = 0.0f;
            if (in) {
                float b = pml_b(gi, gj);
                float rb = 1.0f / (4.0f + b);
                float c2v = c2[g];
                P4 = (8.0f - 4.0f * c2v) * rb;   // center coeff
                Qv = (4.0f - b) * rb;            // old-level coeff
                Rcv = c2v * rb;                  // 4-neighbor-sum coeff
                Sbv = msrc[g] * rb;              // source coeff
            }
            cP4[r][i] = P4; cQ[r][i] = Qv; cRc[r][i] = Rcv; cSb[r][i] = Sbv;
            cur[r][i] = 0.0f; old[r][i] = 0.0f;   // initial condition
        }
    }
    __syncthreads();   // sNbr/sNnbr, sX, smem-zero visible

    unsigned* myFlag = &g_flags[(bi * NBX + bj) * 32];

    #pragma unroll 1
    for (int phase = 0; phase < NPHASE; ++phase) {
        const bool even = (phase & 1) == 0;
        const float* rd1 = even ? g_u1a : g_u1b;
        const float* rd2 = even ? g_u2a : g_u2b;
        float* wr1 = even ? g_u1b : g_u1a;
        float* wr2 = even ? g_u2b : g_u2a;
        const int t0 = phase * KSTEP;

        // Wait for the <=8 neighbor BLOCKS to have finished phase-1.
        if (phase > 0) {
            if (tid < sNnbr) {
                const unsigned* f = &g_flags[sNbr[tid]];
                while (ld_acquire_gpu(f) < (unsigned)phase) { }
            }
            __syncthreads();
        }

        // Refresh halo cells from the read pair (tile cells carried in regs).
        #pragma unroll
        for (int r = 0; r < 2; ++r)
            #pragma unroll
            for (int i = 0; i < 4; ++i)
                if (!inTile[r][i] && inDom[r][i]) {
                    cur[r][i] = __ldcg(&rd1[gidx[r][i]]);
                    old[r][i] = __ldcg(&rd2[gidx[r][i]]);
                }

        // Populate s0 with the current level.
        if (act) {
            *(float4*)(s0 + base0) = make_float4(cur[0][0], cur[0][1], cur[0][2], cur[0][3]);
            *(float4*)(s0 + base1) = make_float4(cur[1][0], cur[1][1], cur[1][2], cur[1][3]);
        }
        __syncthreads();

        // ---- KSTEP in-smem steps, band-pipelined named barriers ----
        #pragma unroll
        for (int s = 0; s < KSTEP; ++s) {
            const float* sc = (s & 1) ? s1 : s0;
            float* sn = (s & 1) ? s0 : s1;
            const float xi = sX[t0 + s];

            if (act) {
                float4 up = *(const float4*)(sc + base0 - PITCH);
                float4 dn = *(const float4*)(sc + base1 + PITCH);
                float lf0 = sc[base0 - 1], rt0 = sc[base0 + 4];
                float lf1 = sc[base1 - 1], rt1 = sc[base1 + 4];

                float n0[4], n1[4];
                n0[0] = (up.x + cur[1][0]) + (lf0 + cur[0][1]);
                n0[1] = (up.y + cur[1][1]) + (cur[0][0] + cur[0][2]);
                n0[2] = (up.z + cur[1][2]) + (cur[0][1] + cur[0][3]);
                n0[3] = (up.w + cur[1][3]) + (cur[0][2] + rt0);
                n1[0] = (cur[0][0] + dn.x) + (lf1 + cur[1][1]);
                n1[1] = (cur[0][1] + dn.y) + (cur[1][0] + cur[1][2]);
                n1[2] = (cur[0][2] + dn.z) + (cur[1][1] + cur[1][3]);
                n1[3] = (cur[0][3] + dn.w) + (cur[1][2] + rt1);

                float v0[4], v1[4];
                #pragma unroll
                for (int i = 0; i < 4; ++i) {
                    float a = cP4[0][i] * cur[0][i];
                    a = fmaf(-cQ[0][i], old[0][i], a);
                    a = fmaf(cRc[0][i], n0[i], a);
                    v0[i] = fmaf(cSb[0][i], xi, a);
                    float b = cP4[1][i] * cur[1][i];
                    b = fmaf(-cQ[1][i], old[1][i], b);
                    b = fmaf(cRc[1][i], n1[i], b);
                    v1[i] = fmaf(cSb[1][i], xi, b);
                }

                *(float4*)(sn + base0) = make_float4(v0[0], v0[1], v0[2], v0[3]);
                *(float4*)(sn + base1) = make_float4(v1[0], v1[1], v1[2], v1[3]);

                #pragma unroll
                for (int i = 0; i < 4; ++i) {
                    old[0][i] = cur[0][i]; cur[0][i] = v0[i];
                    old[1][i] = cur[1][i]; cur[1][i] = v1[i];
                }
            }

            // Band sync (skip after the final step; arrivals skipped too -> balanced).
            if (s < KSTEP - 1) {
                const int p = s & 1;
                if (doArr) {
                    __threadfence_block();           // edge-warp STS visible
                    named_bar_arrive(arrId0 + p, arrCnt);
                }
                named_bar_sync(myId0 + p, myCnt);
            }
        }

        // Write back tile cells.
        if (phase == NPHASE - 1) {
            #pragma unroll
            for (int r = 0; r < 2; ++r)
                #pragma unroll
                for (int i = 0; i < 4; ++i)
                    if (inTile[r][i]) d_final[gidx[r][i]] = cur[r][i];
        } else {
            #pragma unroll
            for (int r = 0; r < 2; ++r)
                #pragma unroll
                for (int i = 0; i < 4; ++i)
                    if (inTile[r][i]) {
                        wr1[gidx[r][i]] = cur[r][i];
                        wr2[gidx[r][i]] = old[r][i];
                    }
            // Publish: all threads' stores ordered via full bar, release by tid0.
            __syncthreads();
            if (tid == 0) st_release_gpu(myFlag, (unsigned)(phase + 1));
        }
    }
}

extern "C" void kernel_launch(void* const* d_in, const int* in_sizes, int n_in,
                              void* d_out, int out_size) {
    const float* x    = (const float*)d_in[0];   // (300,)
    const float* c2   = (const float*)d_in[1];   // (512,512)
    const float* msrc = (const float*)d_in[2];   // (512,512)
    float* out = (float*)d_out;

    wave_zero_kernel<<<NCELL / 256, 256>>>();

    dim3 grd(NBX, NBY);             // (16, 16) = 256 blocks, 2 per SM
    dim3 blk(NGX, NPAIR);           // (16, 26) = 416 threads, 13 warps
    wave_persist_kernel<<<grd, blk>>>(c2, msrc, x, out);
}

// round 16
// speedup vs baseline: 1.3892x; 1.3892x over previous
#include <cuda_runtime.h>

#define NXg 512
#define NYg 512
#define NTg 300
#define NCELL (NXg * NYg)

#define TI 64                     // tile rows per block
#define TJ 32                     // tile cols per block
#define KSTEP 10
#define NPHASE (NTg / KSTEP)      // 30
#define RI (TI + 2 * KSTEP)       // 84 region rows
#define RJ (TJ + 2 * KSTEP)       // 52 region cols (13 float4 groups)
#define NACT 13                   // active column groups
#define NGX 16                    // blockDim.x (3 inert lanes per row for warp alignment)
#define NPAIR 42                  // row pairs (ty)
#define PITCH 68                  // floats per smem row (16B aligned, bank-shifted)
#define SROWS (RI + 2)            // 86 rows incl guard top/bottom
#define SSZ (SROWS * PITCH)       // 5848 floats per level
#define COL0 4                    // smem float offset of region col 0
#define NTHR (NGX * NPAIR)        // 672 threads = 21 warps exactly
#define NBX 16                    // blocks in j
#define NBY 8                     // blocks in i
#define NBLK (NBX * NBY)          // 128 blocks, 1 per SM

// Ping-pong pairs across phases + per-block phase flags (128B padded).
__device__ float g_u1a[NCELL];
__device__ float g_u2a[NCELL];
__device__ float g_u1b[NCELL];
__device__ float g_u2b[NCELL];
__device__ unsigned g_flags[NBLK * 32];

__global__ void wave_zero_kernel() {
    int idx = blockIdx.x * blockDim.x + threadIdx.x;
    if (idx < NBLK * 32) g_flags[idx] = 0u;
    if (idx < NCELL) {
        g_u1a[idx] = 0.0f;
        g_u2a[idx] = 0.0f;
    }
}

__device__ __forceinline__ void st_release_gpu(unsigned* p, unsigned v) {
    asm volatile("st.release.gpu.global.u32 [%0], %1;" :: "l"(p), "r"(v) : "memory");
}
__device__ __forceinline__ unsigned ld_acquire_gpu(const unsigned* p) {
    unsigned v;
    asm volatile("ld.acquire.gpu.global.u32 %0, [%1];" : "=r"(v) : "l"(p) : "memory");
    return v;
}
__device__ __forceinline__ void named_bar_sync(int id, int cnt) {
    asm volatile("bar.sync %0, %1;" :: "r"(id), "r"(cnt) : "memory");
}
__device__ __forceinline__ void named_bar_arrive(int id, int cnt) {
    asm volatile("bar.arrive %0, %1;" :: "r"(id), "r"(cnt) : "memory");
}

// PML ramp: b_vals[k] = 0.5 * (k/20)^3, k in [0,20]
__device__ __forceinline__ float pml_ramp(int k) {
    float t = (float)k * (1.0f / 20.0f);
    return 0.5f * t * t * t;
}

__device__ __forceinline__ float pml_b(int gi, int gj) {
    float bx = 0.0f, by = 0.0f;
    if (gi <= 20) bx = pml_ramp(20 - gi);
    else if (gi >= NXg - 22 && gi <= NXg - 2) bx = pml_ramp(gi - (NXg - 22));
    if (gj <= 20) by = pml_ramp(20 - gj);
    else if (gj >= NYg - 22 && gj <= NYg - 2) by = pml_ramp(gj - (NYg - 22));
    return sqrtf(bx * bx + by * by);
}

__global__ void __launch_bounds__(NTHR)
wave_persist_kernel(const float* __restrict__ c2,
                    const float* __restrict__ msrc,
                    const float* __restrict__ xsrc,
                    float* __restrict__ d_final) {
    __shared__ __align__(16) float s0[SSZ];
    __shared__ __align__(16) float s1[SSZ];
    __shared__ float sX[NTg];
    __shared__ int sNbr[8];
    __shared__ int sNnbr;

    const int tx = threadIdx.x;            // 0..15 (13 active column groups)
    const int ty = threadIdx.y;            // 0..41 row pair
    const int tid = ty * NGX + tx;
    const bool act = (tx < NACT);

    const int bj = blockIdx.x, bi = blockIdx.y;
    const int gi0 = bi * TI;
    const int gj0 = bj * TJ;
    const int ri0 = gi0 - KSTEP;
    const int rj0 = gj0 - KSTEP;
    const int r0 = 2 * ty;                              // first owned region row
    const int base0 = (r0 + 1) * PITCH + COL0 + 4 * tx;
    const int base1 = base0 + PITCH;

    // ---- Band decomposition: 7 bands x 3 warps (6 row pairs each) ----
    // Warp = 2 consecutive row pairs (NGX=16 -> warp-aligned). Band b uses
    // barrier ids {1+2b, 2+2b} alternating on step parity.
    const int band = ty / 6;
    const int lw = (ty % 6) >> 1;          // local warp in band: 0,1,2
    const int myId0 = 1 + 2 * band;
    const int myCnt = (band == 0 || band == 6) ? 128 : 160;
    const bool arrUp = (lw == 0 && band > 0);
    const bool arrDn = (lw == 2 && band < 6);
    const int arrId0 = arrUp ? (1 + 2 * (band - 1)) : (arrDn ? (1 + 2 * (band + 1)) : 0);
    const int arrBand = arrUp ? band - 1 : band + 1;
    const int arrCnt = (arrBand == 0 || arrBand == 6) ? 128 : 160;
    const bool doArr = arrUp || arrDn;

    // Neighbor list (<=8) for the inter-block flag handshake.
    if (tid == 0) {
        int n = 0;
        for (int di = -1; di <= 1; ++di)
            for (int dj = -1; dj <= 1; ++dj) {
                if (di == 0 && dj == 0) continue;
                int ni = bi + di, nj = bj + dj;
                if (ni >= 0 && ni < NBY && nj >= 0 && nj < NBX)
                    sNbr[n++] = (ni * NBX + nj) * 32;
            }
        sNnbr = n;
    }

    // Preload the full source series once.
    for (int k = tid; k < NTg; k += NTHR) sX[k] = xsrc[k];

    // Zero both smem levels incl. guards (guards stay 0 forever).
    for (int k = tid; k < SSZ; k += NTHR) { s0[k] = 0.0f; s1[k] = 0.0f; }

    // ---- One-time: coefficients + cell metadata into registers ----
    float cur[2][4], old[2][4];
    float cP4[2][4], cQ[2][4], cRc[2][4], cSb[2][4];
    int gidx[2][4];
    bool inDom[2][4], inTile[2][4];
    #pragma unroll
    for (int r = 0; r < 2; ++r) {
        int rr = r0 + r;
        int gi = ri0 + rr;
        #pragma unroll
        for (int i = 0; i < 4; ++i) {
            int cc = 4 * tx + i;
            int gj = rj0 + cc;
            bool in = act && (cc < RJ) &&
                      ((unsigned)gi < NXg) && ((unsigned)gj < NYg);
            inDom[r][i] = in;
            inTile[r][i] = in && (rr >= KSTEP) && (rr < KSTEP + TI) &&
                           (cc >= KSTEP) && (cc < KSTEP + TJ);
            int g = in ? (gi * NYg + gj) : 0;
            gidx[r][i] = g;
            float P4 = 0.0f, Qv = 0.0f, Rcv = 0.0f, Sbv = 0.0f;
            if (in) {
                float b = pml_b(gi, gj);
                float rb = 1.0f / (4.0f + b);
                float c2v = c2[g];
                P4 = (8.0f - 4.0f * c2v) * rb;   // center coeff
                Qv = (4.0f - b) * rb;            // old-level coeff
                Rcv = c2v * rb;                  // 4-neighbor-sum coeff
                Sbv = msrc[g] * rb;              // source coeff
            }
            cP4[r][i] = P4; cQ[r][i] = Qv; cRc[r][i] = Rcv; cSb[r][i] = Sbv;
            cur[r][i] = 0.0f; old[r][i] = 0.0f;   // initial condition
        }
    }
    __syncthreads();   // sNbr/sNnbr, sX, smem-zero visible

    unsigned* myFlag = &g_flags[(bi * NBX + bj) * 32];

    #pragma unroll 1
    for (int phase = 0; phase < NPHASE; ++phase) {
        const bool even = (phase & 1) == 0;
        const float* rd1 = even ? g_u1a : g_u1b;
        const float* rd2 = even ? g_u2a : g_u2b;
        float* wr1 = even ? g_u1b : g_u1a;
        float* wr2 = even ? g_u2b : g_u2a;
        const int t0 = phase * KSTEP;

        // Wait for the <=8 neighbor BLOCKS to have finished phase-1.
        if (phase > 0) {
            if (tid < sNnbr) {
                const unsigned* f = &g_flags[sNbr[tid]];
                while (ld_acquire_gpu(f) < (unsigned)phase) { }
            }
            __syncthreads();
        }

        // Refresh halo cells from the read pair (tile cells carried in regs).
        #pragma unroll
        for (int r = 0; r < 2; ++r)
            #pragma unroll
            for (int i = 0; i < 4; ++i)
                if (!inTile[r][i] && inDom[r][i]) {
                    cur[r][i] = __ldcg(&rd1[gidx[r][i]]);
                    old[r][i] = __ldcg(&rd2[gidx[r][i]]);
                }

        // Populate s0 with the current level.
        if (act) {
            *(float4*)(s0 + base0) = make_float4(cur[0][0], cur[0][1], cur[0][2], cur[0][3]);
            *(float4*)(s0 + base1) = make_float4(cur[1][0], cur[1][1], cur[1][2], cur[1][3]);
        }
        __syncthreads();

        // ---- KSTEP in-smem steps, band-pipelined named barriers ----
        #pragma unroll
        for (int s = 0; s < KSTEP; ++s) {
            const float* sc = (s & 1) ? s1 : s0;
            float* sn = (s & 1) ? s0 : s1;
            const float xi = sX[t0 + s];

            if (act) {
                float4 up = *(const float4*)(sc + base0 - PITCH);
                float4 dn = *(const float4*)(sc + base1 + PITCH);
                float lf0 = sc[base0 - 1], rt0 = sc[base0 + 4];
                float lf1 = sc[base1 - 1], rt1 = sc[base1 + 4];

                float n0[4], n1[4];
                n0[0] = (up.x + cur[1][0]) + (lf0 + cur[0][1]);
                n0[1] = (up.y + cur[1][1]) + (cur[0][0] + cur[0][2]);
                n0[2] = (up.z + cur[1][2]) + (cur[0][1] + cur[0][3]);
                n0[3] = (up.w + cur[1][3]) + (cur[0][2] + rt0);
                n1[0] = (cur[0][0] + dn.x) + (lf1 + cur[1][1]);
                n1[1] = (cur[0][1] + dn.y) + (cur[1][0] + cur[1][2]);
                n1[2] = (cur[0][2] + dn.z) + (cur[1][1] + cur[1][3]);
                n1[3] = (cur[0][3] + dn.w) + (cur[1][2] + rt1);

                float v0[4], v1[4];
                #pragma unroll
                for (int i = 0; i < 4; ++i) {
                    float a = cP4[0][i] * cur[0][i];
                    a = fmaf(-cQ[0][i], old[0][i], a);
                    a = fmaf(cRc[0][i], n0[i], a);
                    v0[i] = fmaf(cSb[0][i], xi, a);
                    float b = cP4[1][i] * cur[1][i];
                    b = fmaf(-cQ[1][i], old[1][i], b);
                    b = fmaf(cRc[1][i], n1[i], b);
                    v1[i] = fmaf(cSb[1][i], xi, b);
                }

                *(float4*)(sn + base0) = make_float4(v0[0], v0[1], v0[2], v0[3]);
                *(float4*)(sn + base1) = make_float4(v1[0], v1[1], v1[2], v1[3]);

                #pragma unroll
                for (int i = 0; i < 4; ++i) {
                    old[0][i] = cur[0][i]; cur[0][i] = v0[i];
                    old[1][i] = cur[1][i]; cur[1][i] = v1[i];
                }
            }

            // Band sync. No fence: bar.arrive has release semantics and the
            // paired bar.sync acquire semantics (PTX memory model), so the
            // edge warp's STS above are visible to the released neighbor band.
            // (Skip after the final step; arrivals skipped too -> balanced.)
            if (s < KSTEP - 1) {
                const int p = s & 1;
                if (doArr) named_bar_arrive(arrId0 + p, arrCnt);
                named_bar_sync(myId0 + p, myCnt);
            }
        }

        // Write back tile cells.
        if (phase == NPHASE - 1) {
            #pragma unroll
            for (int r = 0; r < 2; ++r)
                #pragma unroll
                for (int i = 0; i < 4; ++i)
                    if (inTile[r][i]) d_final[gidx[r][i]] = cur[r][i];
        } else {
            #pragma unroll
            for (int r = 0; r < 2; ++r)
                #pragma unroll
                for (int i = 0; i < 4; ++i)
                    if (inTile[r][i]) {
                        wr1[gidx[r][i]] = cur[r][i];
                        wr2[gidx[r][i]] = old[r][i];
                    }
            // Publish: all threads' stores ordered via full bar, release by tid0.
            __syncthreads();
            if (tid == 0) st_release_gpu(myFlag, (unsigned)(phase + 1));
        }
    }
}

extern "C" void kernel_launch(void* const* d_in, const int* in_sizes, int n_in,
                              void* d_out, int out_size) {
    const float* x    = (const float*)d_in[0];   // (300,)
    const float* c2   = (const float*)d_in[1];   // (512,512)
    const float* msrc = (const float*)d_in[2];   // (512,512)
    float* out = (float*)d_out;

    wave_zero_kernel<<<NCELL / 256, 256>>>();

    dim3 grd(NBX, NBY);             // (16, 8) = 128 blocks, 1 per SM
    dim3 blk(NGX, NPAIR);           // (16, 42) = 672 threads, 21 warps
    wave_persist_kernel<<<grd, blk>>>(c2, msrc, x, out);
}

// round 17
// speedup vs baseline: 1.4210x; 1.0229x over previous
#include <cuda_runtime.h>

#define NXg 512
#define NYg 512
#define NTg 300
#define NCELL (NXg * NYg)

#define TI 64                     // tile rows per block
#define TJ 32                     // tile cols per block
#define KSTEP 10
#define NPHASE (NTg / KSTEP)      // 30
#define RI (TI + 2 * KSTEP)       // 84 region rows
#define RJ (TJ + 2 * KSTEP)       // 52 region cols (13 float4 groups)
#define NACT 13                   // active column groups
#define NGX 16                    // blockDim.x (3 inert lanes per row for warp alignment)
#define NPAIR 42                  // row pairs (ty)
#define PITCH 68                  // floats per smem row (16B aligned, bank-shifted)
#define SROWS (RI + 2)            // 86 rows incl guard top/bottom
#define SSZ (SROWS * PITCH)       // 5848 floats per level
#define COL0 4                    // smem float offset of region col 0
#define NTHR (NGX * NPAIR)        // 672 threads = 21 warps exactly
#define NBX 16                    // blocks in j
#define NBY 8                     // blocks in i
#define NBLK (NBX * NBY)          // 128 blocks, 1 per SM

// Ping-pong pairs across phases + per-block phase flags (128B padded).
__device__ float g_u1a[NCELL];
__device__ float g_u2a[NCELL];
__device__ float g_u1b[NCELL];
__device__ float g_u2b[NCELL];
__device__ unsigned g_flags[NBLK * 32];

__global__ void wave_zero_kernel() {
    int idx = blockIdx.x * blockDim.x + threadIdx.x;
    if (idx < NBLK * 32) g_flags[idx] = 0u;
    if (idx < NCELL) {
        g_u1a[idx] = 0.0f;
        g_u2a[idx] = 0.0f;
    }
}

__device__ __forceinline__ void st_release_gpu(unsigned* p, unsigned v) {
    asm volatile("st.release.gpu.global.u32 [%0], %1;" :: "l"(p), "r"(v) : "memory");
}
__device__ __forceinline__ unsigned ld_acquire_gpu(const unsigned* p) {
    unsigned v;
    asm volatile("ld.acquire.gpu.global.u32 %0, [%1];" : "=r"(v) : "l"(p) : "memory");
    return v;
}
__device__ __forceinline__ void named_bar_sync(int id, int cnt) {
    asm volatile("bar.sync %0, %1;" :: "r"(id), "r"(cnt) : "memory");
}
__device__ __forceinline__ void named_bar_arrive(int id, int cnt) {
    asm volatile("bar.arrive %0, %1;" :: "r"(id), "r"(cnt) : "memory");
}

// PML ramp: b_vals[k] = 0.5 * (k/20)^3, k in [0,20]
__device__ __forceinline__ float pml_ramp(int k) {
    float t = (float)k * (1.0f / 20.0f);
    return 0.5f * t * t * t;
}

__device__ __forceinline__ float pml_b(int gi, int gj) {
    float bx = 0.0f, by = 0.0f;
    if (gi <= 20) bx = pml_ramp(20 - gi);
    else if (gi >= NXg - 22 && gi <= NXg - 2) bx = pml_ramp(gi - (NXg - 22));
    if (gj <= 20) by = pml_ramp(20 - gj);
    else if (gj >= NYg - 22 && gj <= NYg - 2) by = pml_ramp(gj - (NYg - 22));
    return sqrtf(bx * bx + by * by);
}

__global__ void __launch_bounds__(NTHR)
wave_persist_kernel(const float* __restrict__ c2,
                    const float* __restrict__ msrc,
                    const float* __restrict__ xsrc,
                    float* __restrict__ d_final) {
    __shared__ __align__(16) float s0[SSZ];
    __shared__ __align__(16) float s1[SSZ];
    __shared__ float sX[NTg];
    __shared__ int sNbr[8];
    __shared__ int sNnbr;

    const int tx = threadIdx.x;            // 0..15 (13 active column groups)
    const int ty = threadIdx.y;            // 0..41 row pair
    const int tid = ty * NGX + tx;
    const bool act = (tx < NACT);

    const int bj = blockIdx.x, bi = blockIdx.y;
    const int gi0 = bi * TI;
    const int gj0 = bj * TJ;
    const int ri0 = gi0 - KSTEP;
    const int rj0 = gj0 - KSTEP;
    const int r0 = 2 * ty;                              // first owned region row
    const int base0 = (r0 + 1) * PITCH + COL0 + 4 * tx;
    const int base1 = base0 + PITCH;

    // ---- Band decomposition: 7 bands x 3 warps (6 row pairs each) ----
    const int band = ty / 6;
    const int lw = (ty % 6) >> 1;          // local warp in band: 0,1,2
    const int myId0 = 1 + 2 * band;
    const int myCnt = (band == 0 || band == 6) ? 128 : 160;
    const bool arrUp = (lw == 0 && band > 0);
    const bool arrDn = (lw == 2 && band < 6);
    const int arrId0 = arrUp ? (1 + 2 * (band - 1)) : (arrDn ? (1 + 2 * (band + 1)) : 0);
    const int arrBand = arrUp ? band - 1 : band + 1;
    const int arrCnt = (arrBand == 0 || arrBand == 6) ? 128 : 160;
    const bool doArr = arrUp || arrDn;

    // Neighbor list (<=8) for the inter-block flag handshake.
    if (tid == 0) {
        int n = 0;
        for (int di = -1; di <= 1; ++di)
            for (int dj = -1; dj <= 1; ++dj) {
                if (di == 0 && dj == 0) continue;
                int ni = bi + di, nj = bj + dj;
                if (ni >= 0 && ni < NBY && nj >= 0 && nj < NBX)
                    sNbr[n++] = (ni * NBX + nj) * 32;
            }
        sNnbr = n;
    }

    // Preload the full source series once.
    for (int k = tid; k < NTg; k += NTHR) sX[k] = xsrc[k];

    // Zero both smem levels incl. guards (guards stay 0 forever).
    for (int k = tid; k < SSZ; k += NTHR) { s0[k] = 0.0f; s1[k] = 0.0f; }

    // ---- One-time: coefficients + cell metadata into registers ----
    float cur[2][4], old[2][4];
    float cP4[2][4], cQ[2][4], cRc[2][4], cSb[2][4];
    int gidx[2][4];
    bool inDom[2][4], inTile[2][4], inFrame[2][4];
    #pragma unroll
    for (int r = 0; r < 2; ++r) {
        int rr = r0 + r;
        int gi = ri0 + rr;
        #pragma unroll
        for (int i = 0; i < 4; ++i) {
            int cc = 4 * tx + i;
            int gj = rj0 + cc;
            bool in = act && (cc < RJ) &&
                      ((unsigned)gi < NXg) && ((unsigned)gj < NYg);
            inDom[r][i] = in;
            bool tile = in && (rr >= KSTEP) && (rr < KSTEP + TI) &&
                        (cc >= KSTEP) && (cc < KSTEP + TJ);
            inTile[r][i] = tile;
            // Frame = outer KSTEP-deep ring of the tile: the only tile cells a
            // neighbor's halo reload ever reads. Interior stores are dead.
            inFrame[r][i] = tile && ((rr < 2 * KSTEP) || (rr >= KSTEP + TI - KSTEP) ||
                                     (cc < 2 * KSTEP) || (cc >= KSTEP + TJ - KSTEP));
            int g = in ? (gi * NYg + gj) : 0;
            gidx[r][i] = g;
            float P4 = 0.0f, Qv = 0.0f, Rcv = 0.0f, Sbv = 0.0f;
            if (in) {
                float b = pml_b(gi, gj);
                float rb = 1.0f / (4.0f + b);
                float c2v = c2[g];
                P4 = (8.0f - 4.0f * c2v) * rb;   // center coeff
                Qv = (4.0f - b) * rb;            // old-level coeff
                Rcv = c2v * rb;                  // 4-neighbor-sum coeff
                Sbv = msrc[g] * rb;              // source coeff
            }
            cP4[r][i] = P4; cQ[r][i] = Qv; cRc[r][i] = Rcv; cSb[r][i] = Sbv;
            cur[r][i] = 0.0f; old[r][i] = 0.0f;   // initial condition
        }
    }
    __syncthreads();   // sNbr/sNnbr, sX, smem-zero visible

    unsigned* myFlag = &g_flags[(bi * NBX + bj) * 32];

    #pragma unroll 1
    for (int phase = 0; phase < NPHASE; ++phase) {
        const bool even = (phase & 1) == 0;
        const float* rd1 = even ? g_u1a : g_u1b;
        const float* rd2 = even ? g_u2a : g_u2b;
        float* wr1 = even ? g_u1b : g_u1a;
        float* wr2 = even ? g_u2b : g_u2a;
        const int t0 = phase * KSTEP;

        // Wait for the <=8 neighbor BLOCKS to have finished phase-1.
        if (phase > 0) {
            if (tid < sNnbr) {
                const unsigned* f = &g_flags[sNbr[tid]];
                while (ld_acquire_gpu(f) < (unsigned)phase) { }
            }
            __syncthreads();
        }

        // Refresh halo cells from the read pair (tile cells carried in regs).
        #pragma unroll
        for (int r = 0; r < 2; ++r)
            #pragma unroll
            for (int i = 0; i < 4; ++i)
                if (!inTile[r][i] && inDom[r][i]) {
                    cur[r][i] = __ldcg(&rd1[gidx[r][i]]);
                    old[r][i] = __ldcg(&rd2[gidx[r][i]]);
                }

        // Populate s0 with the current level.
        if (act) {
            *(float4*)(s0 + base0) = make_float4(cur[0][0], cur[0][1], cur[0][2], cur[0][3]);
            *(float4*)(s0 + base1) = make_float4(cur[1][0], cur[1][1], cur[1][2], cur[1][3]);
        }
        __syncthreads();

        // ---- KSTEP in-smem steps, band-pipelined named barriers ----
        #pragma unroll
        for (int s = 0; s < KSTEP; ++s) {
            const float* sc = (s & 1) ? s1 : s0;
            float* sn = (s & 1) ? s0 : s1;
            const float xi = sX[t0 + s];

            if (act) {
                float4 up = *(const float4*)(sc + base0 - PITCH);
                float4 dn = *(const float4*)(sc + base1 + PITCH);
                float lf0 = sc[base0 - 1], rt0 = sc[base0 + 4];
                float lf1 = sc[base1 - 1], rt1 = sc[base1 + 4];

                float n0[4], n1[4];
                n0[0] = (up.x + cur[1][0]) + (lf0 + cur[0][1]);
                n0[1] = (up.y + cur[1][1]) + (cur[0][0] + cur[0][2]);
                n0[2] = (up.z + cur[1][2]) + (cur[0][1] + cur[0][3]);
                n0[3] = (up.w + cur[1][3]) + (cur[0][2] + rt0);
                n1[0] = (cur[0][0] + dn.x) + (lf1 + cur[1][1]);
                n1[1] = (cur[0][1] + dn.y) + (cur[1][0] + cur[1][2]);
                n1[2] = (cur[0][2] + dn.z) + (cur[1][1] + cur[1][3]);
                n1[3] = (cur[0][3] + dn.w) + (cur[1][2] + rt1);

                float v0[4], v1[4];
                #pragma unroll
                for (int i = 0; i < 4; ++i) {
                    float a = cP4[0][i] * cur[0][i];
                    a = fmaf(-cQ[0][i], old[0][i], a);
                    a = fmaf(cRc[0][i], n0[i], a);
                    v0[i] = fmaf(cSb[0][i], xi, a);
                    float b = cP4[1][i] * cur[1][i];
                    b = fmaf(-cQ[1][i], old[1][i], b);
                    b = fmaf(cRc[1][i], n1[i], b);
                    v1[i] = fmaf(cSb[1][i], xi, b);
                }

                *(float4*)(sn + base0) = make_float4(v0[0], v0[1], v0[2], v0[3]);
                *(float4*)(sn + base1) = make_float4(v1[0], v1[1], v1[2], v1[3]);

                #pragma unroll
                for (int i = 0; i < 4; ++i) {
                    old[0][i] = cur[0][i]; cur[0][i] = v0[i];
                    old[1][i] = cur[1][i]; cur[1][i] = v1[i];
                }
            }

            // Band sync. No fence: bar.arrive release / bar.sync acquire pair
            // orders the edge warp's STS for the released neighbor band.
            if (s < KSTEP - 1) {
                const int p = s & 1;
                if (doArr) named_bar_arrive(arrId0 + p, arrCnt);
                named_bar_sync(myId0 + p, myCnt);
            }
        }

        // Write back ONLY the tile frame (all a neighbor ever reads);
        // interior cells live in registers and their stores are dead.
        if (phase == NPHASE - 1) {
            #pragma unroll
            for (int r = 0; r < 2; ++r)
                #pragma unroll
                for (int i = 0; i < 4; ++i)
                    if (inTile[r][i]) d_final[gidx[r][i]] = cur[r][i];
        } else {
            #pragma unroll
            for (int r = 0; r < 2; ++r)
                #pragma unroll
                for (int i = 0; i < 4; ++i)
                    if (inFrame[r][i]) {
                        wr1[gidx[r][i]] = cur[r][i];
                        wr2[gidx[r][i]] = old[r][i];
                    }
            // Publish: all threads' stores ordered via full bar, release by tid0.
            __syncthreads();
            if (tid == 0) st_release_gpu(myFlag, (unsigned)(phase + 1));
        }
    }
}

extern "C" void kernel_launch(void* const* d_in, const int* in_sizes, int n_in,
                              void* d_out, int out_size) {
    const float* x    = (const float*)d_in[0];   // (300,)
    const float* c2   = (const float*)d_in[1];   // (512,512)
    const float* msrc = (const float*)d_in[2];   // (512,512)
    float* out = (float*)d_out;

    wave_zero_kernel<<<NCELL / 256, 256>>>();

    dim3 grd(NBX, NBY);             // (16, 8) = 128 blocks, 1 per SM
    dim3 blk(NGX, NPAIR);           // (16, 42) = 672 threads, 21 warps
    wave_persist_kernel<<<grd, blk>>>(c2, msrc, x, out);
}